// round 15
// baseline (speedup 1.0000x reference)
#include <cuda_runtime.h>
#include <cuda_bf16.h>
#include <cstdint>
#include <math.h>

#define B_      128
#define G_      2048
#define M_      64
#define T_      128
#define HID_    32
#define KSPLIT  4
#define QLD     72

// ================= scratch (device globals) =================
__device__ float g_C[B_ * M_ * M_];
__device__ float g_covp[KSPLIT * B_ * M_ * M_];
__device__ float g_T1[B_ * G_];
__device__ float g_T2[B_ * G_];
__device__ float g_g[B_ * G_];
// stacked W per batch: rows 0..63 = M = S C S, rows 64..127 = S; bf16 2-term split
__device__ __nv_bfloat16 g_Whi[B_ * 128 * 64];
__device__ __nv_bfloat16 g_Wlo[B_ * 128 * 64];
// A bf16 2-term split, padded [g][QLD] layout (constant all run)
__device__ __nv_bfloat16 g_Bhi[G_ * QLD];
__device__ __nv_bfloat16 g_Blo[G_ * QLD];

__device__ __forceinline__ uint32_t smem_u32(const void* p) {
    uint32_t a;
    asm("{ .reg .u64 t; cvta.to.shared.u64 t, %1; cvt.u32.u64 %0, t; }" : "=r"(a) : "l"(p));
    return a;
}

// ---------------- A -> padded bf16 split (once) ----------------
__global__ void k_presplitA(const float* __restrict__ A) {
    int g = blockIdx.x * 32 + (threadIdx.x & 31);
    int k = threadIdx.x >> 5;
    for (int kk = k; kk < M_; kk += 8) {
        float x = A[(size_t)kk * G_ + g];
        __nv_bfloat16 h = __float2bfloat16(x);
        g_Bhi[(size_t)g * QLD + kk] = h;
        g_Blo[(size_t)g * QLD + kk] = __float2bfloat16(x - __bfloat162float(h));
    }
}

// ---------------- C_b = data_b data_b^T / T + init gamma (once) ----------------
__global__ void k_datacov(const float* __restrict__ data) {
    __shared__ float sh[M_][T_ + 1];
    int b = blockIdx.x;
    for (int i = threadIdx.x; i < G_; i += blockDim.x)
        g_g[(size_t)b * G_ + i] = 1.0f;
    const float* d = data + (size_t)b * M_ * T_;
    for (int i = threadIdx.x; i < M_ * T_; i += blockDim.x)
        sh[i >> 7][i & 127] = d[i];
    __syncthreads();
    for (int idx = threadIdx.x; idx < M_ * M_; idx += blockDim.x) {
        int m = idx >> 6, n = idx & 63;
        float acc = 0.f;
        #pragma unroll 8
        for (int t = 0; t < T_; t++) acc += sh[m][t] * sh[n][t];
        g_C[(size_t)b * 4096 + idx] = acc * (1.0f / (float)T_);
    }
}

// ---------------- cov partial (triangular, fp32 SIMT — known good) ----------------
__global__ void __launch_bounds__(256) k_cov(const float* __restrict__ A) {
    __shared__ float shA[M_][33];
    __shared__ float shg[32];
    int b = blockIdx.x;
    int ks = blockIdx.y;
    int tid = threadIdx.x;

    bool act = tid < 136;
    int ty = 0, tx = 0;
    if (act) {
        float ft = (sqrtf(8.0f * (float)tid + 1.0f) - 1.0f) * 0.5f;
        ty = (int)ft;
        if ((ty + 1) * (ty + 2) / 2 <= tid) ty++;
        if (ty * (ty + 1) / 2 > tid) ty--;
        tx = tid - ty * (ty + 1) / 2;
    }

    float acc[4][4] = {};
    int kbeg = ks * (G_ / KSPLIT), kend = kbeg + (G_ / KSPLIT);
    for (int k0 = kbeg; k0 < kend; k0 += 32) {
        for (int i = tid; i < M_ * 32; i += 256) {
            int r = i >> 5, c = i & 31;
            shA[r][c] = A[(size_t)r * G_ + k0 + c];
        }
        if (tid < 32) shg[tid] = g_g[(size_t)b * G_ + k0 + tid];
        __syncthreads();
        if (act) {
            #pragma unroll 4
            for (int k = 0; k < 32; k++) {
                float gv = shg[k];
                float am[4], an[4];
                #pragma unroll
                for (int i = 0; i < 4; i++) am[i] = shA[ty * 4 + i][k] * gv;
                #pragma unroll
                for (int j = 0; j < 4; j++) an[j] = shA[tx * 4 + j][k];
                #pragma unroll
                for (int i = 0; i < 4; i++)
                    #pragma unroll
                    for (int j = 0; j < 4; j++) acc[i][j] += am[i] * an[j];
            }
        }
        __syncthreads();
    }
    if (act) {
        float* dst = g_covp + ((size_t)ks * B_ + b) * 4096;
        #pragma unroll
        for (int i = 0; i < 4; i++)
            #pragma unroll
            for (int j = 0; j < 4; j++) {
                dst[(ty * 4 + i) * 64 + tx * 4 + j] = acc[i][j];
                dst[(tx * 4 + j) * 64 + ty * 4 + i] = acc[i][j];
            }
    }
}

// ---------------- fused: panel-4 GJ inverse + (Tmp=S@C, M=Tmp@S) + W emit ----------------
#define ILD 68
#define IM_AUGT 0
#define IM_F1   (128 * ILD)
#define IM_F2E  (IM_F1 + 64)
#define IM_F3E  (IM_F2E + 64)
#define IM_F4E  (IM_F3E + 64)
#define IM_F2R  (IM_F4E + 64)
#define IM_F3R  (IM_F2R + 64)
#define IM_SS   (IM_F3R + 64)
#define IM_SC   (IM_SS + 64 * 65)
#define IM_ST   (IM_SC + 64 * 64)
#define IMSMEM  ((IM_ST + 64 * 65) * 4)

__device__ __forceinline__ float wpick(float v0, float v1, int p) {
    float a = __shfl_sync(0xffffffffu, v0, p & 31);
    float b = __shfl_sync(0xffffffffu, v1, p & 31);
    return (p < 32) ? a : b;
}
__device__ __forceinline__ void wargmax(float e0, float e1, bool u0, bool u1,
                                        int lane, int& bi_out, float& bv_out) {
    float v0 = u0 ? fabsf(e0) : -1.0f;
    float v1 = u1 ? fabsf(e1) : -1.0f;
    int bi; float best, bv;
    if (v1 > v0) { best = v1; bi = lane + 32; bv = e1; }
    else         { best = v0; bi = lane;      bv = e0; }
    #pragma unroll
    for (int o = 16; o > 0; o >>= 1) {
        float ob = __shfl_xor_sync(0xffffffffu, best, o);
        int   oi = __shfl_xor_sync(0xffffffffu, bi, o);
        float ov = __shfl_xor_sync(0xffffffffu, bv, o);
        if (ob > best || (ob == best && oi < bi)) { best = ob; bi = oi; bv = ov; }
    }
    bi_out = bi; bv_out = bv;
}

__global__ void __launch_bounds__(256) k_inv_mm() {
    extern __shared__ float sm[];
    float* augT = sm + IM_AUGT;
    float* f1   = sm + IM_F1;
    float* f2e  = sm + IM_F2E;
    float* f3e  = sm + IM_F3E;
    float* f4e  = sm + IM_F4E;
    float* f2r  = sm + IM_F2R;
    float* f3r  = sm + IM_F3R;
    float* sS   = sm + IM_SS;
    float* sC   = sm + IM_SC;
    float* sT   = sm + IM_ST;
    __shared__ int s_p[4];
    __shared__ float s_ip[4];
    __shared__ int pivk[M_];

    int b = blockIdx.x, tid = threadIdx.x;
    int wid = tid >> 5, lane = tid & 31;

    for (int idx = tid; idx < M_ * M_; idx += 256) {
        int i = idx >> 6, c = idx & 63;
        float v = g_covp[(size_t)b * 4096 + idx]
                + g_covp[(size_t)(B_ + b) * 4096 + idx]
                + g_covp[(size_t)(2 * B_ + b) * 4096 + idx]
                + g_covp[(size_t)(3 * B_ + b) * 4096 + idx];
        if (i == c) v += 0.1f;
        augT[c * ILD + i] = v;
        augT[(64 + c) * ILD + i] = (i == c) ? 1.0f : 0.0f;
        sC[idx] = g_C[(size_t)b * 4096 + idx];
    }
    __syncthreads();

    bool u0 = true, u1 = true;

    for (int k = 0; k < M_; k += 4) {
        if (wid == 0) {
            float c0 = augT[k * ILD + lane], c1 = augT[k * ILD + lane + 32];
            int p1; float pv1;
            wargmax(c0, c1, u0, u1, lane, p1, pv1);
            if (p1 == lane) u0 = false;
            if (p1 == lane + 32) u1 = false;
            if (lane == 0) { s_p[0] = p1; s_ip[0] = 1.0f / pv1; pivk[k] = p1; }
        } else if (wid == 1) {
            f1[lane] = augT[k * ILD + lane];
            f1[lane + 32] = augT[k * ILD + lane + 32];
        } else if (wid == 2) {
            f2r[lane] = augT[(k + 1) * ILD + lane];
            f2r[lane + 32] = augT[(k + 1) * ILD + lane + 32];
        } else if (wid == 3) {
            f3r[lane] = augT[(k + 2) * ILD + lane];
            f3r[lane + 32] = augT[(k + 2) * ILD + lane + 32];
        }
        __syncthreads();

        if (wid == 0) {
            int p1 = s_p[0]; float ip1 = s_ip[0];
            float f1_0 = f1[lane], f1_1 = f1[lane + 32];

            float g0 = f2r[lane], g1 = f2r[lane + 32];
            float rn12 = wpick(g0, g1, p1) * ip1;
            float e2_0 = g0 - f1_0 * rn12;
            float e2_1 = g1 - f1_1 * rn12;
            if (lane == p1)      e2_0 = rn12;
            if (lane + 32 == p1) e2_1 = rn12;
            int p2; float pv2;
            wargmax(e2_0, e2_1, u0, u1, lane, p2, pv2);
            if (p2 == lane) u0 = false;
            if (p2 == lane + 32) u1 = false;
            float ip2 = 1.0f / pv2;
            f2e[lane] = e2_0; f2e[lane + 32] = e2_1;

            float h0 = f3r[lane], h1 = f3r[lane + 32];
            float rn13 = wpick(h0, h1, p1) * ip1;
            float rn23 = (wpick(h0, h1, p2) - wpick(f1_0, f1_1, p2) * rn13) * ip2;
            float e3_0 = h0 - f1_0 * rn13 - e2_0 * rn23;
            float e3_1 = h1 - f1_1 * rn13 - e2_1 * rn23;
            if (lane == p1)      e3_0 = rn13 - e2_0 * rn23;
            if (lane + 32 == p1) e3_1 = rn13 - e2_1 * rn23;
            if (lane == p2)      e3_0 = rn23;
            if (lane + 32 == p2) e3_1 = rn23;
            int p3; float pv3;
            wargmax(e3_0, e3_1, u0, u1, lane, p3, pv3);
            if (p3 == lane) u0 = false;
            if (p3 == lane + 32) u1 = false;
            float ip3 = 1.0f / pv3;
            f3e[lane] = e3_0; f3e[lane + 32] = e3_1;

            float q0 = augT[(k + 3) * ILD + lane], q1 = augT[(k + 3) * ILD + lane + 32];
            float rn14 = wpick(q0, q1, p1) * ip1;
            float rn24 = (wpick(q0, q1, p2) - wpick(f1_0, f1_1, p2) * rn14) * ip2;
            float rn34 = (wpick(q0, q1, p3) - wpick(f1_0, f1_1, p3) * rn14
                          - wpick(e2_0, e2_1, p3) * rn24) * ip3;
            float e4_0 = q0 - f1_0 * rn14 - e2_0 * rn24 - e3_0 * rn34;
            float e4_1 = q1 - f1_1 * rn14 - e2_1 * rn24 - e3_1 * rn34;
            if (lane == p1)      e4_0 = rn14 - e2_0 * rn24 - e3_0 * rn34;
            if (lane + 32 == p1) e4_1 = rn14 - e2_1 * rn24 - e3_1 * rn34;
            if (lane == p2)      e4_0 = rn24 - e3_0 * rn34;
            if (lane + 32 == p2) e4_1 = rn24 - e3_1 * rn34;
            if (lane == p3)      e4_0 = rn34;
            if (lane + 32 == p3) e4_1 = rn34;
            int p4; float pv4;
            wargmax(e4_0, e4_1, u0, u1, lane, p4, pv4);
            if (p4 == lane) u0 = false;
            if (p4 == lane + 32) u1 = false;
            f4e[lane] = e4_0; f4e[lane + 32] = e4_1;

            if (lane == 0) {
                s_p[1] = p2; s_ip[1] = ip2; pivk[k + 1] = p2;
                s_p[2] = p3; s_ip[2] = ip3; pivk[k + 2] = p3;
                s_p[3] = p4; s_ip[3] = 1.0f / pv4; pivk[k + 3] = p4;
            }
        }
        __syncthreads();

        {
            int jj = tid & 127;
            int half = tid >> 7;
            int rb = half * 32;
            int p1 = s_p[0], p2 = s_p[1], p3 = s_p[2], p4 = s_p[3];
            float ip1 = s_ip[0], ip2 = s_ip[1], ip3 = s_ip[2], ip4 = s_ip[3];
            float* col = augT + jj * ILD;
            float rn1 = col[p1] * ip1;
            float rn2 = (col[p2] - f1[p2] * rn1) * ip2;
            float rn3 = (col[p3] - f1[p3] * rn1 - f2e[p3] * rn2) * ip3;
            float rn4 = (col[p4] - f1[p4] * rn1 - f2e[p4] * rn2 - f3e[p4] * rn3) * ip4;
            if (rn1 != 0.0f || rn2 != 0.0f || rn3 != 0.0f || rn4 != 0.0f) {
                #pragma unroll
                for (int i4 = rb; i4 < rb + 32; i4 += 4) {
                    float4 a1 = *(const float4*)&f1[i4];
                    float4 a2 = *(const float4*)&f2e[i4];
                    float4 a3 = *(const float4*)&f3e[i4];
                    float4 a4 = *(const float4*)&f4e[i4];
                    float4 v  = *(const float4*)&col[i4];
                    v.x -= a1.x * rn1 + a2.x * rn2 + a3.x * rn3 + a4.x * rn4;
                    v.y -= a1.y * rn1 + a2.y * rn2 + a3.y * rn3 + a4.y * rn4;
                    v.z -= a1.z * rn1 + a2.z * rn2 + a3.z * rn3 + a4.z * rn4;
                    v.w -= a1.w * rn1 + a2.w * rn2 + a3.w * rn3 + a4.w * rn4;
                    *(float4*)&col[i4] = v;
                }
                if ((p1 >> 5) == half)
                    col[p1] = rn1 - f2e[p1] * rn2 - f3e[p1] * rn3 - f4e[p1] * rn4;
                if ((p2 >> 5) == half)
                    col[p2] = rn2 - f3e[p2] * rn3 - f4e[p2] * rn4;
                if ((p3 >> 5) == half)
                    col[p3] = rn3 - f4e[p3] * rn4;
                if ((p4 >> 5) == half)
                    col[p4] = rn4;
            }
        }
        __syncthreads();
    }

    for (int idx = tid; idx < M_ * M_; idx += 256) {
        int kk = idx >> 6, c = idx & 63;
        float v = augT[(64 + c) * ILD + pivk[kk]];
        sS[kk * 65 + c] = v;
        __nv_bfloat16 h = __float2bfloat16(v);
        g_Whi[(size_t)b * 8192 + (size_t)(64 + kk) * 64 + c] = h;
        g_Wlo[(size_t)b * 8192 + (size_t)(64 + kk) * 64 + c] =
            __float2bfloat16(v - __bfloat162float(h));
    }
    __syncthreads();

    int tx = tid & 15, ty = tid >> 4;
    {
        float acc[4][4] = {};
        #pragma unroll 4
        for (int k = 0; k < M_; k++) {
            float xm[4], yn[4];
            #pragma unroll
            for (int i = 0; i < 4; i++) xm[i] = sS[(ty * 4 + i) * 65 + k];
            #pragma unroll
            for (int jj = 0; jj < 4; jj++) yn[jj] = sC[k * 64 + tx * 4 + jj];
            #pragma unroll
            for (int i = 0; i < 4; i++)
                #pragma unroll
                for (int jj = 0; jj < 4; jj++) acc[i][jj] += xm[i] * yn[jj];
        }
        #pragma unroll
        for (int i = 0; i < 4; i++)
            #pragma unroll
            for (int jj = 0; jj < 4; jj++)
                sT[(ty * 4 + i) * 65 + tx * 4 + jj] = acc[i][jj];
    }
    __syncthreads();
    {
        float acc[4][4] = {};
        #pragma unroll 4
        for (int k = 0; k < M_; k++) {
            float xm[4], yn[4];
            #pragma unroll
            for (int i = 0; i < 4; i++) xm[i] = sT[(ty * 4 + i) * 65 + k];
            #pragma unroll
            for (int jj = 0; jj < 4; jj++) yn[jj] = sS[k * 65 + tx * 4 + jj];
            #pragma unroll
            for (int i = 0; i < 4; i++)
                #pragma unroll
                for (int jj = 0; jj < 4; jj++) acc[i][jj] += xm[i] * yn[jj];
        }
        #pragma unroll
        for (int i = 0; i < 4; i++)
            #pragma unroll
            for (int jj = 0; jj < 4; jj++) {
                int r = ty * 4 + i, c = tx * 4 + jj;
                float v = acc[i][jj];
                __nv_bfloat16 h = __float2bfloat16(v);
                g_Whi[(size_t)b * 8192 + (size_t)r * 64 + c] = h;
                g_Wlo[(size_t)b * 8192 + (size_t)r * 64 + c] =
                    __float2bfloat16(v - __bfloat162float(h));
            }
    }
}

// ---------------- quadratic forms: mma.sync bf16 split + ldmatrix frag loads ----------------
#define QNC 128
#define QOFF_WHI   0
#define QOFF_WLO   (QOFF_WHI + 128 * QLD * 2)
#define QOFF_BHI   (QOFF_WLO + 128 * QLD * 2)
#define QOFF_BLO   (QOFF_BHI + QNC * QLD * 2)
#define QOFF_SPART (QOFF_BLO + QNC * QLD * 2)
#define QSMEM_TOTAL (QOFF_SPART + 4 * QNC * 4)

__device__ __forceinline__ void mma16816(float d[4], const uint32_t a[4], const uint32_t b[2]) {
    asm volatile(
        "mma.sync.aligned.m16n8k16.row.col.f32.bf16.bf16.f32 "
        "{%0,%1,%2,%3}, {%4,%5,%6,%7}, {%8,%9}, {%0,%1,%2,%3};"
        : "+f"(d[0]), "+f"(d[1]), "+f"(d[2]), "+f"(d[3])
        : "r"(a[0]), "r"(a[1]), "r"(a[2]), "r"(a[3]), "r"(b[0]), "r"(b[1]));
}
__device__ __forceinline__ void ldsm_x4(uint32_t& r0, uint32_t& r1, uint32_t& r2, uint32_t& r3,
                                        uint32_t addr) {
    asm volatile("ldmatrix.sync.aligned.m8n8.x4.shared.b16 {%0,%1,%2,%3}, [%4];"
        : "=r"(r0), "=r"(r1), "=r"(r2), "=r"(r3) : "r"(addr));
}

__global__ void __launch_bounds__(512) k_quad_mma() {
    extern __shared__ char smem[];
    __nv_bfloat16* sWhi = (__nv_bfloat16*)(smem + QOFF_WHI);
    __nv_bfloat16* sWlo = (__nv_bfloat16*)(smem + QOFF_WLO);
    __nv_bfloat16* sBhi = (__nv_bfloat16*)(smem + QOFF_BHI);
    __nv_bfloat16* sBlo = (__nv_bfloat16*)(smem + QOFF_BLO);
    float* spart = (float*)(smem + QOFF_SPART);

    int tid = threadIdx.x;
    int wid = tid >> 5, lane = tid & 31;
    int wm = wid & 3;
    int wn = wid >> 2;
    int g0 = blockIdx.x * QNC;
    int b  = blockIdx.y;

    {
        const uint4* srcH = (const uint4*)(g_Whi + (size_t)b * 8192);
        const uint4* srcL = (const uint4*)(g_Wlo + (size_t)b * 8192);
        for (int i = tid; i < 1024; i += 512) {
            int r = i >> 3, c = i & 7;
            *(uint4*)&sWhi[r * QLD + c * 8] = srcH[i];
            *(uint4*)&sWlo[r * QLD + c * 8] = srcL[i];
        }
    }
    {
        const __nv_bfloat16* srcH = g_Bhi + (size_t)g0 * QLD;
        const __nv_bfloat16* srcL = g_Blo + (size_t)g0 * QLD;
        for (int i = tid; i < QNC * 8; i += 512) {
            int g = i >> 3, c = i & 7;
            *(uint4*)&sBhi[g * QLD + c * 8] = *(const uint4*)&srcH[(size_t)g * QLD + c * 8];
            *(uint4*)&sBlo[g * QLD + c * 8] = *(const uint4*)&srcL[(size_t)g * QLD + c * 8];
        }
    }
    __syncthreads();

    // ldmatrix lane addressing
    int l8   = lane & 7;
    int lidx = lane >> 3;            // 0..3
    // A: matrices (m0-7,kb),(m8-15,kb),(m0-7,kb+8),(m8-15,kb+8)
    int a_row_base = wm * 32 + l8 + (lidx & 1) * 8;   // + f*16
    int a_kadd = (lidx >> 1) * 8;
    // B: matrices (t,kb),(t,kb+8),(t+1,kb),(t+1,kb+8)
    int b_row_base = wn * 32 + (lidx >> 1) * 8 + l8;  // + t*8
    int b_kadd = (lidx & 1) * 8;

    uint32_t baseW[2] = { smem_u32(sWhi), smem_u32(sWlo) };
    uint32_t baseB[2] = { smem_u32(sBhi), smem_u32(sBlo) };

    int lr = lane >> 2;
    int cq = (lane & 3) * 2;

    float d[2][4][4];
    #pragma unroll
    for (int f = 0; f < 2; f++)
        #pragma unroll
        for (int t = 0; t < 4; t++)
            #pragma unroll
            for (int q = 0; q < 4; q++) d[f][t][q] = 0.0f;

    #pragma unroll
    for (int sp = 0; sp < 3; sp++) {
        uint32_t wb = baseW[sp == 2 ? 1 : 0];
        uint32_t bb_base = baseB[sp == 1 ? 1 : 0];
        #pragma unroll
        for (int ks = 0; ks < 4; ks++) {
            int kb = ks * 16;
            uint32_t a[2][4];
            #pragma unroll
            for (int f = 0; f < 2; f++) {
                uint32_t addr = wb + (uint32_t)(((a_row_base + f * 16) * QLD) + kb + a_kadd) * 2;
                ldsm_x4(a[f][0], a[f][1], a[f][2], a[f][3], addr);
            }
            uint32_t bfr[8];
            #pragma unroll
            for (int tp = 0; tp < 2; tp++) {   // tile pairs (0,1) and (2,3)
                uint32_t addr = bb_base + (uint32_t)(((b_row_base + tp * 16) * QLD) + kb + b_kadd) * 2;
                ldsm_x4(bfr[tp * 4 + 0], bfr[tp * 4 + 1], bfr[tp * 4 + 2], bfr[tp * 4 + 3], addr);
            }
            #pragma unroll
            for (int t = 0; t < 4; t++) {
                uint32_t bv[2] = { bfr[t * 2], bfr[t * 2 + 1] };
                mma16816(d[0][t], a[0], bv);
                mma16816(d[1][t], a[1], bv);
            }
        }
    }

    #pragma unroll
    for (int t = 0; t < 4; t++) {
        int gcol = wn * 32 + t * 8 + cq;
        float p0 = 0.0f, p1 = 0.0f;
        #pragma unroll
        for (int f = 0; f < 2; f++) {
            int m0 = (wm * 32 + f * 16 + lr) & 63;
            int m8 = m0 + 8;
            float a00 = __bfloat162float(sBhi[gcol * QLD + m0]) + __bfloat162float(sBlo[gcol * QLD + m0]);
            float a10 = __bfloat162float(sBhi[gcol * QLD + m8]) + __bfloat162float(sBlo[gcol * QLD + m8]);
            float a01 = __bfloat162float(sBhi[(gcol + 1) * QLD + m0]) + __bfloat162float(sBlo[(gcol + 1) * QLD + m0]);
            float a11 = __bfloat162float(sBhi[(gcol + 1) * QLD + m8]) + __bfloat162float(sBlo[(gcol + 1) * QLD + m8]);
            p0 += d[f][t][0] * a00 + d[f][t][2] * a10;
            p1 += d[f][t][1] * a01 + d[f][t][3] * a11;
        }
        #pragma unroll
        for (int o = 4; o < 32; o <<= 1) {
            p0 += __shfl_xor_sync(0xffffffffu, p0, o);
            p1 += __shfl_xor_sync(0xffffffffu, p1, o);
        }
        if (lane < 4) {
            spart[wm * QNC + gcol] = p0;
            spart[wm * QNC + gcol + 1] = p1;
        }
    }
    __syncthreads();
    if (tid < QNC) {
        int g = tid;
        float t1 = spart[g] + spart[QNC + g];
        float t2 = spart[2 * QNC + g] + spart[3 * QNC + g];
        g_T1[(size_t)b * G_ + g0 + g] = t1;
        g_T2[(size_t)b * G_ + g0 + g] = fabsf(t2);
    }
}

// ---------------- per-gridpoint MLP ----------------
__global__ void k_mlp(const float* __restrict__ W1, const float* __restrict__ B1,
                      const float* __restrict__ W2, const float* __restrict__ B2,
                      const float* __restrict__ W3, const float* __restrict__ B3,
                      int it, int last, float* __restrict__ out) {
    int g = blockIdx.x;
    int b = threadIdx.x;
    __shared__ float sW1[96], sB1[32], sW2[1024], sB2[32], sW3[32], sB3;
    size_t gidx = (size_t)it * G_ + g;
    const float* w1 = W1 + gidx * 96;
    const float* w2 = W2 + gidx * 1024;
    if (b < 96) sW1[b] = w1[b];
    if (b < 32) {
        sB1[b] = B1[gidx * 32 + b];
        sB2[b] = B2[gidx * 32 + b];
        sW3[b] = W3[gidx * 32 + b];
    }
    if (b == 0) sB3 = B3[gidx];
    for (int i = b; i < 1024; i += 128) sW2[i] = w2[i];
    __syncthreads();

    float x0 = g_T1[(size_t)b * G_ + g];
    float x1 = g_T2[(size_t)b * G_ + g];
    float x2 = g_g[(size_t)b * G_ + g];

    float h[HID_];
    #pragma unroll
    for (int j = 0; j < HID_; j++) {
        float v = x0 * sW1[j] + x1 * sW1[32 + j] + x2 * sW1[64 + j] + sB1[j];
        h[j] = fmaxf(v, 0.0f);
    }
    float h2[HID_];
    #pragma unroll
    for (int j = 0; j < HID_; j++) h2[j] = sB2[j];
    #pragma unroll
    for (int j = 0; j < HID_; j++) {
        float hv = h[j];
        #pragma unroll
        for (int k = 0; k < HID_; k++) h2[k] += hv * sW2[j * 32 + k];
    }
    float o = sB3;
    #pragma unroll
    for (int k = 0; k < HID_; k++) o += fmaxf(h2[k], 0.0f) * sW3[k];

    if (last) out[(size_t)b * G_ + g] = o;
    else      g_g[(size_t)b * G_ + g] = o;
}

// ---------------- launch ----------------
extern "C" void kernel_launch(void* const* d_in, const int* in_sizes, int n_in,
                              void* d_out, int out_size) {
    const float* data = (const float*)d_in[0];
    const float* A    = (const float*)d_in[1];
    const float* W1   = (const float*)d_in[2];
    const float* b1   = (const float*)d_in[3];
    const float* W2   = (const float*)d_in[4];
    const float* b2   = (const float*)d_in[5];
    const float* W3   = (const float*)d_in[6];
    const float* b3   = (const float*)d_in[7];
    float* out = (float*)d_out;

    static int smem_set = 0;
    if (!smem_set) {
        cudaFuncSetAttribute(k_quad_mma, cudaFuncAttributeMaxDynamicSharedMemorySize, QSMEM_TOTAL);
        cudaFuncSetAttribute(k_inv_mm, cudaFuncAttributeMaxDynamicSharedMemorySize, IMSMEM);
        smem_set = 1;
    }

    k_presplitA<<<G_ / 32, 256>>>(A);
    k_datacov<<<B_, 256>>>(data);
    for (int it = 0; it < 3; it++) {
        k_cov<<<dim3(B_, KSPLIT), 256>>>(A);
        k_inv_mm<<<B_, 256, IMSMEM>>>();
        k_quad_mma<<<dim3(G_ / QNC, B_), 512, QSMEM_TOTAL>>>();
        k_mlp<<<G_, 128>>>(W1, b1, W2, b2, W3, b3, it, it == 2 ? 1 : 0, out);
    }
}

// round 16
// speedup vs baseline: 1.0348x; 1.0348x over previous
#include <cuda_runtime.h>
#include <cuda_bf16.h>
#include <cstdint>
#include <math.h>

#define B_      128
#define G_      2048
#define M_      64
#define T_      128
#define HID_    32
#define KSPLIT  4
#define QLD     72

// ================= scratch (device globals) =================
__device__ float g_C[B_ * M_ * M_];
__device__ float g_covp[KSPLIT * B_ * M_ * M_];
__device__ float g_T1[B_ * G_];
__device__ float g_T2[B_ * G_];
__device__ float g_g[B_ * G_];
__device__ __nv_bfloat16 g_Whi[B_ * 128 * 64];
__device__ __nv_bfloat16 g_Wlo[B_ * 128 * 64];
__device__ __nv_bfloat16 g_Bhi[G_ * QLD];
__device__ __nv_bfloat16 g_Blo[G_ * QLD];

// ---------------- A -> padded bf16 split (once) ----------------
__global__ void k_presplitA(const float* __restrict__ A) {
    int g = blockIdx.x * 32 + (threadIdx.x & 31);
    int k = threadIdx.x >> 5;
    for (int kk = k; kk < M_; kk += 8) {
        float x = A[(size_t)kk * G_ + g];
        __nv_bfloat16 h = __float2bfloat16(x);
        g_Bhi[(size_t)g * QLD + kk] = h;
        g_Blo[(size_t)g * QLD + kk] = __float2bfloat16(x - __bfloat162float(h));
    }
}

// ---------------- C_b = data_b data_b^T / T + init gamma (once) ----------------
__global__ void k_datacov(const float* __restrict__ data) {
    __shared__ float sh[M_][T_ + 1];
    int b = blockIdx.x;
    for (int i = threadIdx.x; i < G_; i += blockDim.x)
        g_g[(size_t)b * G_ + i] = 1.0f;
    const float* d = data + (size_t)b * M_ * T_;
    for (int i = threadIdx.x; i < M_ * T_; i += blockDim.x)
        sh[i >> 7][i & 127] = d[i];
    __syncthreads();
    for (int idx = threadIdx.x; idx < M_ * M_; idx += blockDim.x) {
        int m = idx >> 6, n = idx & 63;
        float acc = 0.f;
        #pragma unroll 8
        for (int t = 0; t < T_; t++) acc += sh[m][t] * sh[n][t];
        g_C[(size_t)b * 4096 + idx] = acc * (1.0f / (float)T_);
    }
}

// ---------------- cov partial (triangular, fp32, transposed smem + LDS.128) ----------------
__global__ void __launch_bounds__(256) k_cov(const float* __restrict__ A) {
    __shared__ __align__(16) float shA[32][68];   // [k][m], rows 16B-aligned
    __shared__ float shg[32];
    int b = blockIdx.x;
    int ks = blockIdx.y;
    int tid = threadIdx.x;

    bool act = tid < 136;
    int ty = 0, tx = 0;
    if (act) {
        float ft = (sqrtf(8.0f * (float)tid + 1.0f) - 1.0f) * 0.5f;
        ty = (int)ft;
        if ((ty + 1) * (ty + 2) / 2 <= tid) ty++;
        if (ty * (ty + 1) / 2 > tid) ty--;
        tx = tid - ty * (ty + 1) / 2;
    }

    float acc[4][4] = {};
    int kbeg = ks * (G_ / KSPLIT), kend = kbeg + (G_ / KSPLIT);
    for (int k0 = kbeg; k0 < kend; k0 += 32) {
        for (int i = tid; i < M_ * 32; i += 256) {
            int r = i >> 5, c = i & 31;             // r = m, c = k
            shA[c][r] = A[(size_t)r * G_ + k0 + c];
        }
        if (tid < 32) shg[tid] = g_g[(size_t)b * G_ + k0 + tid];
        __syncthreads();
        if (act) {
            #pragma unroll 4
            for (int k = 0; k < 32; k++) {
                float gv = shg[k];
                float4 am4 = *(const float4*)&shA[k][ty * 4];
                float4 an4 = *(const float4*)&shA[k][tx * 4];
                float am[4] = { am4.x * gv, am4.y * gv, am4.z * gv, am4.w * gv };
                float an[4] = { an4.x, an4.y, an4.z, an4.w };
                #pragma unroll
                for (int i = 0; i < 4; i++)
                    #pragma unroll
                    for (int j = 0; j < 4; j++) acc[i][j] += am[i] * an[j];
            }
        }
        __syncthreads();
    }
    if (act) {
        float* dst = g_covp + ((size_t)ks * B_ + b) * 4096;
        #pragma unroll
        for (int i = 0; i < 4; i++)
            #pragma unroll
            for (int j = 0; j < 4; j++) {
                dst[(ty * 4 + i) * 64 + tx * 4 + j] = acc[i][j];
                dst[(tx * 4 + j) * 64 + ty * 4 + i] = acc[i][j];
            }
    }
}

// ---------------- fused: panel-4 GJ inverse + (Tmp=S@C, M=Tmp@S) + W emit ----------------
#define ILD 68
#define IM_AUGT 0
#define IM_F1   (128 * ILD)
#define IM_F2E  (IM_F1 + 64)
#define IM_F3E  (IM_F2E + 64)
#define IM_F4E  (IM_F3E + 64)
#define IM_F2R  (IM_F4E + 64)
#define IM_F3R  (IM_F2R + 64)
#define IM_SS   (IM_F3R + 64)
#define IM_SC   (IM_SS + 64 * 65)
#define IM_ST   (IM_SC + 64 * 64)
#define IMSMEM  ((IM_ST + 64 * 65) * 4)

__device__ __forceinline__ float wpick(float v0, float v1, int p) {
    float a = __shfl_sync(0xffffffffu, v0, p & 31);
    float b = __shfl_sync(0xffffffffu, v1, p & 31);
    return (p < 32) ? a : b;
}
__device__ __forceinline__ void wargmax(float e0, float e1, bool u0, bool u1,
                                        int lane, int& bi_out, float& bv_out) {
    float v0 = u0 ? fabsf(e0) : -1.0f;
    float v1 = u1 ? fabsf(e1) : -1.0f;
    int bi; float best, bv;
    if (v1 > v0) { best = v1; bi = lane + 32; bv = e1; }
    else         { best = v0; bi = lane;      bv = e0; }
    #pragma unroll
    for (int o = 16; o > 0; o >>= 1) {
        float ob = __shfl_xor_sync(0xffffffffu, best, o);
        int   oi = __shfl_xor_sync(0xffffffffu, bi, o);
        float ov = __shfl_xor_sync(0xffffffffu, bv, o);
        if (ob > best || (ob == best && oi < bi)) { best = ob; bi = oi; bv = ov; }
    }
    bi_out = bi; bv_out = bv;
}

__global__ void __launch_bounds__(256) k_inv_mm() {
    extern __shared__ float sm[];
    float* augT = sm + IM_AUGT;
    float* f1   = sm + IM_F1;
    float* f2e  = sm + IM_F2E;
    float* f3e  = sm + IM_F3E;
    float* f4e  = sm + IM_F4E;
    float* f2r  = sm + IM_F2R;
    float* f3r  = sm + IM_F3R;
    float* sS   = sm + IM_SS;
    float* sC   = sm + IM_SC;
    float* sT   = sm + IM_ST;
    __shared__ int s_p[4];
    __shared__ float s_ip[4];
    __shared__ int pivk[M_];

    int b = blockIdx.x, tid = threadIdx.x;
    int wid = tid >> 5, lane = tid & 31;

    for (int idx = tid; idx < M_ * M_; idx += 256) {
        int i = idx >> 6, c = idx & 63;
        float v = g_covp[(size_t)b * 4096 + idx]
                + g_covp[(size_t)(B_ + b) * 4096 + idx]
                + g_covp[(size_t)(2 * B_ + b) * 4096 + idx]
                + g_covp[(size_t)(3 * B_ + b) * 4096 + idx];
        if (i == c) v += 0.1f;
        augT[c * ILD + i] = v;
        augT[(64 + c) * ILD + i] = (i == c) ? 1.0f : 0.0f;
        sC[idx] = g_C[(size_t)b * 4096 + idx];
    }
    __syncthreads();

    bool u0 = true, u1 = true;

    for (int k = 0; k < M_; k += 4) {
        if (wid == 0) {
            float c0 = augT[k * ILD + lane], c1 = augT[k * ILD + lane + 32];
            int p1; float pv1;
            wargmax(c0, c1, u0, u1, lane, p1, pv1);
            if (p1 == lane) u0 = false;
            if (p1 == lane + 32) u1 = false;
            if (lane == 0) { s_p[0] = p1; s_ip[0] = 1.0f / pv1; pivk[k] = p1; }
        } else if (wid == 1) {
            f1[lane] = augT[k * ILD + lane];
            f1[lane + 32] = augT[k * ILD + lane + 32];
        } else if (wid == 2) {
            f2r[lane] = augT[(k + 1) * ILD + lane];
            f2r[lane + 32] = augT[(k + 1) * ILD + lane + 32];
        } else if (wid == 3) {
            f3r[lane] = augT[(k + 2) * ILD + lane];
            f3r[lane + 32] = augT[(k + 2) * ILD + lane + 32];
        }
        __syncthreads();

        if (wid == 0) {
            int p1 = s_p[0]; float ip1 = s_ip[0];
            float f1_0 = f1[lane], f1_1 = f1[lane + 32];

            float g0 = f2r[lane], g1 = f2r[lane + 32];
            float rn12 = wpick(g0, g1, p1) * ip1;
            float e2_0 = g0 - f1_0 * rn12;
            float e2_1 = g1 - f1_1 * rn12;
            if (lane == p1)      e2_0 = rn12;
            if (lane + 32 == p1) e2_1 = rn12;
            int p2; float pv2;
            wargmax(e2_0, e2_1, u0, u1, lane, p2, pv2);
            if (p2 == lane) u0 = false;
            if (p2 == lane + 32) u1 = false;
            float ip2 = 1.0f / pv2;
            f2e[lane] = e2_0; f2e[lane + 32] = e2_1;

            float h0 = f3r[lane], h1 = f3r[lane + 32];
            float rn13 = wpick(h0, h1, p1) * ip1;
            float rn23 = (wpick(h0, h1, p2) - wpick(f1_0, f1_1, p2) * rn13) * ip2;
            float e3_0 = h0 - f1_0 * rn13 - e2_0 * rn23;
            float e3_1 = h1 - f1_1 * rn13 - e2_1 * rn23;
            if (lane == p1)      e3_0 = rn13 - e2_0 * rn23;
            if (lane + 32 == p1) e3_1 = rn13 - e2_1 * rn23;
            if (lane == p2)      e3_0 = rn23;
            if (lane + 32 == p2) e3_1 = rn23;
            int p3; float pv3;
            wargmax(e3_0, e3_1, u0, u1, lane, p3, pv3);
            if (p3 == lane) u0 = false;
            if (p3 == lane + 32) u1 = false;
            float ip3 = 1.0f / pv3;
            f3e[lane] = e3_0; f3e[lane + 32] = e3_1;

            float q0 = augT[(k + 3) * ILD + lane], q1 = augT[(k + 3) * ILD + lane + 32];
            float rn14 = wpick(q0, q1, p1) * ip1;
            float rn24 = (wpick(q0, q1, p2) - wpick(f1_0, f1_1, p2) * rn14) * ip2;
            float rn34 = (wpick(q0, q1, p3) - wpick(f1_0, f1_1, p3) * rn14
                          - wpick(e2_0, e2_1, p3) * rn24) * ip3;
            float e4_0 = q0 - f1_0 * rn14 - e2_0 * rn24 - e3_0 * rn34;
            float e4_1 = q1 - f1_1 * rn14 - e2_1 * rn24 - e3_1 * rn34;
            if (lane == p1)      e4_0 = rn14 - e2_0 * rn24 - e3_0 * rn34;
            if (lane + 32 == p1) e4_1 = rn14 - e2_1 * rn24 - e3_1 * rn34;
            if (lane == p2)      e4_0 = rn24 - e3_0 * rn34;
            if (lane + 32 == p2) e4_1 = rn24 - e3_1 * rn34;
            if (lane == p3)      e4_0 = rn34;
            if (lane + 32 == p3) e4_1 = rn34;
            int p4; float pv4;
            wargmax(e4_0, e4_1, u0, u1, lane, p4, pv4);
            if (p4 == lane) u0 = false;
            if (p4 == lane + 32) u1 = false;
            f4e[lane] = e4_0; f4e[lane + 32] = e4_1;

            if (lane == 0) {
                s_p[1] = p2; s_ip[1] = ip2; pivk[k + 1] = p2;
                s_p[2] = p3; s_ip[2] = ip3; pivk[k + 2] = p3;
                s_p[3] = p4; s_ip[3] = 1.0f / pv4; pivk[k + 3] = p4;
            }
        }
        __syncthreads();

        {
            int jj = tid & 127;
            int half = tid >> 7;
            int rb = half * 32;
            int p1 = s_p[0], p2 = s_p[1], p3 = s_p[2], p4 = s_p[3];
            float ip1 = s_ip[0], ip2 = s_ip[1], ip3 = s_ip[2], ip4 = s_ip[3];
            float* col = augT + jj * ILD;
            float rn1 = col[p1] * ip1;
            float rn2 = (col[p2] - f1[p2] * rn1) * ip2;
            float rn3 = (col[p3] - f1[p3] * rn1 - f2e[p3] * rn2) * ip3;
            float rn4 = (col[p4] - f1[p4] * rn1 - f2e[p4] * rn2 - f3e[p4] * rn3) * ip4;
            if (rn1 != 0.0f || rn2 != 0.0f || rn3 != 0.0f || rn4 != 0.0f) {
                #pragma unroll
                for (int i4 = rb; i4 < rb + 32; i4 += 4) {
                    float4 a1 = *(const float4*)&f1[i4];
                    float4 a2 = *(const float4*)&f2e[i4];
                    float4 a3 = *(const float4*)&f3e[i4];
                    float4 a4 = *(const float4*)&f4e[i4];
                    float4 v  = *(const float4*)&col[i4];
                    v.x -= a1.x * rn1 + a2.x * rn2 + a3.x * rn3 + a4.x * rn4;
                    v.y -= a1.y * rn1 + a2.y * rn2 + a3.y * rn3 + a4.y * rn4;
                    v.z -= a1.z * rn1 + a2.z * rn2 + a3.z * rn3 + a4.z * rn4;
                    v.w -= a1.w * rn1 + a2.w * rn2 + a3.w * rn3 + a4.w * rn4;
                    *(float4*)&col[i4] = v;
                }
                if ((p1 >> 5) == half)
                    col[p1] = rn1 - f2e[p1] * rn2 - f3e[p1] * rn3 - f4e[p1] * rn4;
                if ((p2 >> 5) == half)
                    col[p2] = rn2 - f3e[p2] * rn3 - f4e[p2] * rn4;
                if ((p3 >> 5) == half)
                    col[p3] = rn3 - f4e[p3] * rn4;
                if ((p4 >> 5) == half)
                    col[p4] = rn4;
            }
        }
        __syncthreads();
    }

    for (int idx = tid; idx < M_ * M_; idx += 256) {
        int kk = idx >> 6, c = idx & 63;
        float v = augT[(64 + c) * ILD + pivk[kk]];
        sS[kk * 65 + c] = v;
        __nv_bfloat16 h = __float2bfloat16(v);
        g_Whi[(size_t)b * 8192 + (size_t)(64 + kk) * 64 + c] = h;
        g_Wlo[(size_t)b * 8192 + (size_t)(64 + kk) * 64 + c] =
            __float2bfloat16(v - __bfloat162float(h));
    }
    __syncthreads();

    int tx = tid & 15, ty = tid >> 4;
    {
        float acc[4][4] = {};
        #pragma unroll 4
        for (int k = 0; k < M_; k++) {
            float xm[4], yn[4];
            #pragma unroll
            for (int i = 0; i < 4; i++) xm[i] = sS[(ty * 4 + i) * 65 + k];
            #pragma unroll
            for (int jj = 0; jj < 4; jj++) yn[jj] = sC[k * 64 + tx * 4 + jj];
            #pragma unroll
            for (int i = 0; i < 4; i++)
                #pragma unroll
                for (int jj = 0; jj < 4; jj++) acc[i][jj] += xm[i] * yn[jj];
        }
        #pragma unroll
        for (int i = 0; i < 4; i++)
            #pragma unroll
            for (int jj = 0; jj < 4; jj++)
                sT[(ty * 4 + i) * 65 + tx * 4 + jj] = acc[i][jj];
    }
    __syncthreads();
    {
        float acc[4][4] = {};
        #pragma unroll 4
        for (int k = 0; k < M_; k++) {
            float xm[4], yn[4];
            #pragma unroll
            for (int i = 0; i < 4; i++) xm[i] = sT[(ty * 4 + i) * 65 + k];
            #pragma unroll
            for (int jj = 0; jj < 4; jj++) yn[jj] = sS[k * 65 + tx * 4 + jj];
            #pragma unroll
            for (int i = 0; i < 4; i++)
                #pragma unroll
                for (int jj = 0; jj < 4; jj++) acc[i][jj] += xm[i] * yn[jj];
        }
        #pragma unroll
        for (int i = 0; i < 4; i++)
            #pragma unroll
            for (int jj = 0; jj < 4; jj++) {
                int r = ty * 4 + i, c = tx * 4 + jj;
                float v = acc[i][jj];
                __nv_bfloat16 h = __float2bfloat16(v);
                g_Whi[(size_t)b * 8192 + (size_t)r * 64 + c] = h;
                g_Wlo[(size_t)b * 8192 + (size_t)r * 64 + c] =
                    __float2bfloat16(v - __bfloat162float(h));
            }
    }
}

// ---------------- quadratic forms (R14 proven): mma.sync bf16 split, 16 warps ----------------
#define QNC 128
#define QOFF_WHI   0
#define QOFF_WLO   (QOFF_WHI + 128 * QLD * 2)
#define QOFF_BHI   (QOFF_WLO + 128 * QLD * 2)
#define QOFF_BLO   (QOFF_BHI + QNC * QLD * 2)
#define QOFF_SPART (QOFF_BLO + QNC * QLD * 2)
#define QSMEM_TOTAL (QOFF_SPART + 4 * QNC * 4)

__device__ __forceinline__ void mma16816(float d[4], const uint32_t a[4], const uint32_t b[2]) {
    asm volatile(
        "mma.sync.aligned.m16n8k16.row.col.f32.bf16.bf16.f32 "
        "{%0,%1,%2,%3}, {%4,%5,%6,%7}, {%8,%9}, {%0,%1,%2,%3};"
        : "+f"(d[0]), "+f"(d[1]), "+f"(d[2]), "+f"(d[3])
        : "r"(a[0]), "r"(a[1]), "r"(a[2]), "r"(a[3]), "r"(b[0]), "r"(b[1]));
}

__global__ void __launch_bounds__(512) k_quad_mma() {
    extern __shared__ char smem[];
    __nv_bfloat16* sWhi = (__nv_bfloat16*)(smem + QOFF_WHI);
    __nv_bfloat16* sWlo = (__nv_bfloat16*)(smem + QOFF_WLO);
    __nv_bfloat16* sBhi = (__nv_bfloat16*)(smem + QOFF_BHI);
    __nv_bfloat16* sBlo = (__nv_bfloat16*)(smem + QOFF_BLO);
    float* spart = (float*)(smem + QOFF_SPART);

    int tid = threadIdx.x;
    int wid = tid >> 5, lane = tid & 31;
    int wm = wid & 3;
    int wn = wid >> 2;
    int g0 = blockIdx.x * QNC;
    int b  = blockIdx.y;

    {
        const uint4* srcH = (const uint4*)(g_Whi + (size_t)b * 8192);
        const uint4* srcL = (const uint4*)(g_Wlo + (size_t)b * 8192);
        for (int i = tid; i < 1024; i += 512) {
            int r = i >> 3, c = i & 7;
            *(uint4*)&sWhi[r * QLD + c * 8] = srcH[i];
            *(uint4*)&sWlo[r * QLD + c * 8] = srcL[i];
        }
    }
    {
        const __nv_bfloat16* srcH = g_Bhi + (size_t)g0 * QLD;
        const __nv_bfloat16* srcL = g_Blo + (size_t)g0 * QLD;
        for (int i = tid; i < QNC * 8; i += 512) {
            int g = i >> 3, c = i & 7;
            *(uint4*)&sBhi[g * QLD + c * 8] = *(const uint4*)&srcH[(size_t)g * QLD + c * 8];
            *(uint4*)&sBlo[g * QLD + c * 8] = *(const uint4*)&srcL[(size_t)g * QLD + c * 8];
        }
    }
    __syncthreads();

    int lr = lane >> 2;
    int cq = (lane & 3) * 2;

    float d[2][4][4];
    #pragma unroll
    for (int f = 0; f < 2; f++)
        #pragma unroll
        for (int t = 0; t < 4; t++)
            #pragma unroll
            for (int q = 0; q < 4; q++) d[f][t][q] = 0.0f;

    #pragma unroll
    for (int sp = 0; sp < 3; sp++) {
        const __nv_bfloat16* Wsrc = (sp == 2) ? sWlo : sWhi;
        const __nv_bfloat16* Bsrc = (sp == 1) ? sBlo : sBhi;
        #pragma unroll
        for (int ks = 0; ks < 4; ks++) {
            int kb = ks * 16;
            uint32_t a[2][4];
            #pragma unroll
            for (int f = 0; f < 2; f++) {
                int r0 = wm * 32 + f * 16 + lr;
                a[f][0] = *(const uint32_t*)&Wsrc[r0 * QLD + kb + cq];
                a[f][1] = *(const uint32_t*)&Wsrc[(r0 + 8) * QLD + kb + cq];
                a[f][2] = *(const uint32_t*)&Wsrc[r0 * QLD + kb + cq + 8];
                a[f][3] = *(const uint32_t*)&Wsrc[(r0 + 8) * QLD + kb + cq + 8];
            }
            #pragma unroll
            for (int t = 0; t < 4; t++) {
                int gl = wn * 32 + t * 8 + lr;
                uint32_t bb[2];
                bb[0] = *(const uint32_t*)&Bsrc[gl * QLD + kb + cq];
                bb[1] = *(const uint32_t*)&Bsrc[gl * QLD + kb + cq + 8];
                mma16816(d[0][t], a[0], bb);
                mma16816(d[1][t], a[1], bb);
            }
        }
    }

    #pragma unroll
    for (int t = 0; t < 4; t++) {
        int gcol = wn * 32 + t * 8 + cq;
        float p0 = 0.0f, p1 = 0.0f;
        #pragma unroll
        for (int f = 0; f < 2; f++) {
            int m0 = (wm * 32 + f * 16 + lr) & 63;
            int m8 = m0 + 8;
            float a00 = __bfloat162float(sBhi[gcol * QLD + m0]) + __bfloat162float(sBlo[gcol * QLD + m0]);
            float a10 = __bfloat162float(sBhi[gcol * QLD + m8]) + __bfloat162float(sBlo[gcol * QLD + m8]);
            float a01 = __bfloat162float(sBhi[(gcol + 1) * QLD + m0]) + __bfloat162float(sBlo[(gcol + 1) * QLD + m0]);
            float a11 = __bfloat162float(sBhi[(gcol + 1) * QLD + m8]) + __bfloat162float(sBlo[(gcol + 1) * QLD + m8]);
            p0 += d[f][t][0] * a00 + d[f][t][2] * a10;
            p1 += d[f][t][1] * a01 + d[f][t][3] * a11;
        }
        #pragma unroll
        for (int o = 4; o < 32; o <<= 1) {
            p0 += __shfl_xor_sync(0xffffffffu, p0, o);
            p1 += __shfl_xor_sync(0xffffffffu, p1, o);
        }
        if (lane < 4) {
            spart[wm * QNC + gcol] = p0;
            spart[wm * QNC + gcol + 1] = p1;
        }
    }
    __syncthreads();
    if (tid < QNC) {
        int g = tid;
        float t1 = spart[g] + spart[QNC + g];
        float t2 = spart[2 * QNC + g] + spart[3 * QNC + g];
        g_T1[(size_t)b * G_ + g0 + g] = t1;
        g_T2[(size_t)b * G_ + g0 + g] = fabsf(t2);
    }
}

// ---------------- per-gridpoint MLP ----------------
__global__ void k_mlp(const float* __restrict__ W1, const float* __restrict__ B1,
                      const float* __restrict__ W2, const float* __restrict__ B2,
                      const float* __restrict__ W3, const float* __restrict__ B3,
                      int it, int last, float* __restrict__ out) {
    int g = blockIdx.x;
    int b = threadIdx.x;
    __shared__ float sW1[96], sB1[32], sW2[1024], sB2[32], sW3[32], sB3;
    size_t gidx = (size_t)it * G_ + g;
    const float* w1 = W1 + gidx * 96;
    const float* w2 = W2 + gidx * 1024;
    if (b < 96) sW1[b] = w1[b];
    if (b < 32) {
        sB1[b] = B1[gidx * 32 + b];
        sB2[b] = B2[gidx * 32 + b];
        sW3[b] = W3[gidx * 32 + b];
    }
    if (b == 0) sB3 = B3[gidx];
    for (int i = b; i < 1024; i += 128) sW2[i] = w2[i];
    __syncthreads();

    float x0 = g_T1[(size_t)b * G_ + g];
    float x1 = g_T2[(size_t)b * G_ + g];
    float x2 = g_g[(size_t)b * G_ + g];

    float h[HID_];
    #pragma unroll
    for (int j = 0; j < HID_; j++) {
        float v = x0 * sW1[j] + x1 * sW1[32 + j] + x2 * sW1[64 + j] + sB1[j];
        h[j] = fmaxf(v, 0.0f);
    }
    float h2[HID_];
    #pragma unroll
    for (int j = 0; j < HID_; j++) h2[j] = sB2[j];
    #pragma unroll
    for (int j = 0; j < HID_; j++) {
        float hv = h[j];
        #pragma unroll
        for (int k = 0; k < HID_; k++) h2[k] += hv * sW2[j * 32 + k];
    }
    float o = sB3;
    #pragma unroll
    for (int k = 0; k < HID_; k++) o += fmaxf(h2[k], 0.0f) * sW3[k];

    if (last) out[(size_t)b * G_ + g] = o;
    else      g_g[(size_t)b * G_ + g] = o;
}

// ---------------- launch ----------------
extern "C" void kernel_launch(void* const* d_in, const int* in_sizes, int n_in,
                              void* d_out, int out_size) {
    const float* data = (const float*)d_in[0];
    const float* A    = (const float*)d_in[1];
    const float* W1   = (const float*)d_in[2];
    const float* b1   = (const float*)d_in[3];
    const float* W2   = (const float*)d_in[4];
    const float* b2   = (const float*)d_in[5];
    const float* W3   = (const float*)d_in[6];
    const float* b3   = (const float*)d_in[7];
    float* out = (float*)d_out;

    static int smem_set = 0;
    if (!smem_set) {
        cudaFuncSetAttribute(k_quad_mma, cudaFuncAttributeMaxDynamicSharedMemorySize, QSMEM_TOTAL);
        cudaFuncSetAttribute(k_inv_mm, cudaFuncAttributeMaxDynamicSharedMemorySize, IMSMEM);
        smem_set = 1;
    }

    k_presplitA<<<G_ / 32, 256>>>(A);
    k_datacov<<<B_, 256>>>(data);
    for (int it = 0; it < 3; it++) {
        k_cov<<<dim3(B_, KSPLIT), 256>>>(A);
        k_inv_mm<<<B_, 256, IMSMEM>>>();
        k_quad_mma<<<dim3(G_ / QNC, B_), 512, QSMEM_TOTAL>>>();
        k_mlp<<<G_, 128>>>(W1, b1, W2, b2, W3, b3, it, it == 2 ? 1 : 0, out);
    }
}

// round 17
// speedup vs baseline: 1.0409x; 1.0059x over previous
#include <cuda_runtime.h>
#include <cuda_bf16.h>
#include <cstdint>
#include <math.h>

#define B_      128
#define G_      2048
#define M_      64
#define T_      128
#define HID_    32
#define KSPLIT  4
#define QLD     72

typedef unsigned long long u64t;
__device__ __forceinline__ u64t pk2(float lo, float hi) {
    u64t r; asm("mov.b64 %0, {%1, %2};" : "=l"(r) : "f"(lo), "f"(hi)); return r;
}
__device__ __forceinline__ void upk2(u64t v, float& lo, float& hi) {
    asm("mov.b64 {%0, %1}, %2;" : "=f"(lo), "=f"(hi) : "l"(v));
}
__device__ __forceinline__ u64t fma2(u64t a, u64t b, u64t c) {
    u64t r; asm("fma.rn.f32x2 %0, %1, %2, %3;" : "=l"(r) : "l"(a), "l"(b), "l"(c)); return r;
}
__device__ __forceinline__ u64t mul2(u64t a, u64t b) {
    u64t r; asm("mul.rn.f32x2 %0, %1, %2;" : "=l"(r) : "l"(a), "l"(b)); return r;
}

// ================= scratch (device globals) =================
__device__ float g_C[B_ * M_ * M_];
__device__ float g_covp[KSPLIT * B_ * M_ * M_];
__device__ float g_T1[B_ * G_];
__device__ float g_T2[B_ * G_];
__device__ float g_g[B_ * G_];
__device__ __nv_bfloat16 g_Whi[B_ * 128 * 64];
__device__ __nv_bfloat16 g_Wlo[B_ * 128 * 64];
__device__ __nv_bfloat16 g_Bhi[G_ * QLD];
__device__ __nv_bfloat16 g_Blo[G_ * QLD];

// ---------------- A -> padded bf16 split (once) ----------------
__global__ void k_presplitA(const float* __restrict__ A) {
    int g = blockIdx.x * 32 + (threadIdx.x & 31);
    int k = threadIdx.x >> 5;
    for (int kk = k; kk < M_; kk += 8) {
        float x = A[(size_t)kk * G_ + g];
        __nv_bfloat16 h = __float2bfloat16(x);
        g_Bhi[(size_t)g * QLD + kk] = h;
        g_Blo[(size_t)g * QLD + kk] = __float2bfloat16(x - __bfloat162float(h));
    }
}

// ---------------- C_b = data_b data_b^T / T + init gamma (once) ----------------
__global__ void k_datacov(const float* __restrict__ data) {
    __shared__ float sh[M_][T_ + 1];
    int b = blockIdx.x;
    for (int i = threadIdx.x; i < G_; i += blockDim.x)
        g_g[(size_t)b * G_ + i] = 1.0f;
    const float* d = data + (size_t)b * M_ * T_;
    for (int i = threadIdx.x; i < M_ * T_; i += blockDim.x)
        sh[i >> 7][i & 127] = d[i];
    __syncthreads();
    for (int idx = threadIdx.x; idx < M_ * M_; idx += blockDim.x) {
        int m = idx >> 6, n = idx & 63;
        float acc = 0.f;
        #pragma unroll 8
        for (int t = 0; t < T_; t++) acc += sh[m][t] * sh[n][t];
        g_C[(size_t)b * 4096 + idx] = acc * (1.0f / (float)T_);
    }
}

// ---------------- cov partial (triangular, fp32 via fma.rn.f32x2) ----------------
__global__ void __launch_bounds__(256) k_cov(const float* __restrict__ A) {
    __shared__ __align__(16) float shA[32][68];   // [k][m]
    __shared__ float shg[32];
    int b = blockIdx.x;
    int ks = blockIdx.y;
    int tid = threadIdx.x;

    bool act = tid < 136;
    int ty = 0, tx = 0;
    if (act) {
        float ft = (sqrtf(8.0f * (float)tid + 1.0f) - 1.0f) * 0.5f;
        ty = (int)ft;
        if ((ty + 1) * (ty + 2) / 2 <= tid) ty++;
        if (ty * (ty + 1) / 2 > tid) ty--;
        tx = tid - ty * (ty + 1) / 2;
    }

    u64t acc2[4][2] = {};   // acc2[i][p] covers j = 2p, 2p+1
    int kbeg = ks * (G_ / KSPLIT), kend = kbeg + (G_ / KSPLIT);
    for (int k0 = kbeg; k0 < kend; k0 += 32) {
        for (int i = tid; i < M_ * 32; i += 256) {
            int r = i >> 5, c = i & 31;
            shA[c][r] = A[(size_t)r * G_ + k0 + c];
        }
        if (tid < 32) shg[tid] = g_g[(size_t)b * G_ + k0 + tid];
        __syncthreads();
        if (act) {
            #pragma unroll 4
            for (int k = 0; k < 32; k++) {
                float gv = shg[k];
                ulonglong2 amu = *(const ulonglong2*)&shA[k][ty * 4];
                ulonglong2 anu = *(const ulonglong2*)&shA[k][tx * 4];
                u64t gv2 = pk2(gv, gv);
                u64t am01 = mul2(amu.x, gv2);
                u64t am23 = mul2(amu.y, gv2);
                float a0, a1, a2, a3;
                upk2(am01, a0, a1);
                upk2(am23, a2, a3);
                u64t d0 = pk2(a0, a0), d1 = pk2(a1, a1), d2 = pk2(a2, a2), d3 = pk2(a3, a3);
                acc2[0][0] = fma2(d0, anu.x, acc2[0][0]);
                acc2[0][1] = fma2(d0, anu.y, acc2[0][1]);
                acc2[1][0] = fma2(d1, anu.x, acc2[1][0]);
                acc2[1][1] = fma2(d1, anu.y, acc2[1][1]);
                acc2[2][0] = fma2(d2, anu.x, acc2[2][0]);
                acc2[2][1] = fma2(d2, anu.y, acc2[2][1]);
                acc2[3][0] = fma2(d3, anu.x, acc2[3][0]);
                acc2[3][1] = fma2(d3, anu.y, acc2[3][1]);
            }
        }
        __syncthreads();
    }
    if (act) {
        float acc[4][4];
        #pragma unroll
        for (int i = 0; i < 4; i++) {
            upk2(acc2[i][0], acc[i][0], acc[i][1]);
            upk2(acc2[i][1], acc[i][2], acc[i][3]);
        }
        float* dst = g_covp + ((size_t)ks * B_ + b) * 4096;
        #pragma unroll
        for (int i = 0; i < 4; i++)
            #pragma unroll
            for (int j = 0; j < 4; j++) {
                dst[(ty * 4 + i) * 64 + tx * 4 + j] = acc[i][j];
                dst[(tx * 4 + j) * 64 + ty * 4 + i] = acc[i][j];
            }
    }
}

// ---------------- fused: panel-4 GJ inverse + (Tmp=S@C, M=Tmp@S) + W emit ----------------
#define ILD 68
#define IM_AUGT 0
#define IM_F1   (128 * ILD)
#define IM_F2E  (IM_F1 + 64)
#define IM_F3E  (IM_F2E + 64)
#define IM_F4E  (IM_F3E + 64)
#define IM_F2R  (IM_F4E + 64)
#define IM_F3R  (IM_F2R + 64)
#define IM_SS   (IM_F3R + 64)
#define IM_SC   (IM_SS + 64 * 65)
#define IM_ST   (IM_SC + 64 * 64)
#define IMSMEM  ((IM_ST + 64 * 65) * 4)

__device__ __forceinline__ float wpick(float v0, float v1, int p) {
    float a = __shfl_sync(0xffffffffu, v0, p & 31);
    float b = __shfl_sync(0xffffffffu, v1, p & 31);
    return (p < 32) ? a : b;
}
__device__ __forceinline__ void wargmax(float e0, float e1, bool u0, bool u1,
                                        int lane, int& bi_out, float& bv_out) {
    float v0 = u0 ? fabsf(e0) : -1.0f;
    float v1 = u1 ? fabsf(e1) : -1.0f;
    int bi; float best, bv;
    if (v1 > v0) { best = v1; bi = lane + 32; bv = e1; }
    else         { best = v0; bi = lane;      bv = e0; }
    #pragma unroll
    for (int o = 16; o > 0; o >>= 1) {
        float ob = __shfl_xor_sync(0xffffffffu, best, o);
        int   oi = __shfl_xor_sync(0xffffffffu, bi, o);
        float ov = __shfl_xor_sync(0xffffffffu, bv, o);
        if (ob > best || (ob == best && oi < bi)) { best = ob; bi = oi; bv = ov; }
    }
    bi_out = bi; bv_out = bv;
}

__global__ void __launch_bounds__(256) k_inv_mm() {
    extern __shared__ float sm[];
    float* augT = sm + IM_AUGT;
    float* f1   = sm + IM_F1;
    float* f2e  = sm + IM_F2E;
    float* f3e  = sm + IM_F3E;
    float* f4e  = sm + IM_F4E;
    float* f2r  = sm + IM_F2R;
    float* f3r  = sm + IM_F3R;
    float* sS   = sm + IM_SS;
    float* sC   = sm + IM_SC;
    float* sT   = sm + IM_ST;
    __shared__ int s_p[4];
    __shared__ float s_ip[4];
    __shared__ int pivk[M_];

    int b = blockIdx.x, tid = threadIdx.x;
    int wid = tid >> 5, lane = tid & 31;

    for (int idx = tid; idx < M_ * M_; idx += 256) {
        int i = idx >> 6, c = idx & 63;
        float v = g_covp[(size_t)b * 4096 + idx]
                + g_covp[(size_t)(B_ + b) * 4096 + idx]
                + g_covp[(size_t)(2 * B_ + b) * 4096 + idx]
                + g_covp[(size_t)(3 * B_ + b) * 4096 + idx];
        if (i == c) v += 0.1f;
        augT[c * ILD + i] = v;
        augT[(64 + c) * ILD + i] = (i == c) ? 1.0f : 0.0f;
        sC[idx] = g_C[(size_t)b * 4096 + idx];
    }
    __syncthreads();

    bool u0 = true, u1 = true;

    for (int k = 0; k < M_; k += 4) {
        if (wid == 0) {
            float c0 = augT[k * ILD + lane], c1 = augT[k * ILD + lane + 32];
            int p1; float pv1;
            wargmax(c0, c1, u0, u1, lane, p1, pv1);
            if (p1 == lane) u0 = false;
            if (p1 == lane + 32) u1 = false;
            if (lane == 0) { s_p[0] = p1; s_ip[0] = 1.0f / pv1; pivk[k] = p1; }
        } else if (wid == 1) {
            f1[lane] = augT[k * ILD + lane];
            f1[lane + 32] = augT[k * ILD + lane + 32];
        } else if (wid == 2) {
            f2r[lane] = augT[(k + 1) * ILD + lane];
            f2r[lane + 32] = augT[(k + 1) * ILD + lane + 32];
        } else if (wid == 3) {
            f3r[lane] = augT[(k + 2) * ILD + lane];
            f3r[lane + 32] = augT[(k + 2) * ILD + lane + 32];
        }
        __syncthreads();

        if (wid == 0) {
            int p1 = s_p[0]; float ip1 = s_ip[0];
            float f1_0 = f1[lane], f1_1 = f1[lane + 32];

            float g0 = f2r[lane], g1 = f2r[lane + 32];
            float rn12 = wpick(g0, g1, p1) * ip1;
            float e2_0 = g0 - f1_0 * rn12;
            float e2_1 = g1 - f1_1 * rn12;
            if (lane == p1)      e2_0 = rn12;
            if (lane + 32 == p1) e2_1 = rn12;
            int p2; float pv2;
            wargmax(e2_0, e2_1, u0, u1, lane, p2, pv2);
            if (p2 == lane) u0 = false;
            if (p2 == lane + 32) u1 = false;
            float ip2 = 1.0f / pv2;
            f2e[lane] = e2_0; f2e[lane + 32] = e2_1;

            float h0 = f3r[lane], h1 = f3r[lane + 32];
            float rn13 = wpick(h0, h1, p1) * ip1;
            float rn23 = (wpick(h0, h1, p2) - wpick(f1_0, f1_1, p2) * rn13) * ip2;
            float e3_0 = h0 - f1_0 * rn13 - e2_0 * rn23;
            float e3_1 = h1 - f1_1 * rn13 - e2_1 * rn23;
            if (lane == p1)      e3_0 = rn13 - e2_0 * rn23;
            if (lane + 32 == p1) e3_1 = rn13 - e2_1 * rn23;
            if (lane == p2)      e3_0 = rn23;
            if (lane + 32 == p2) e3_1 = rn23;
            int p3; float pv3;
            wargmax(e3_0, e3_1, u0, u1, lane, p3, pv3);
            if (p3 == lane) u0 = false;
            if (p3 == lane + 32) u1 = false;
            float ip3 = 1.0f / pv3;
            f3e[lane] = e3_0; f3e[lane + 32] = e3_1;

            float q0 = augT[(k + 3) * ILD + lane], q1 = augT[(k + 3) * ILD + lane + 32];
            float rn14 = wpick(q0, q1, p1) * ip1;
            float rn24 = (wpick(q0, q1, p2) - wpick(f1_0, f1_1, p2) * rn14) * ip2;
            float rn34 = (wpick(q0, q1, p3) - wpick(f1_0, f1_1, p3) * rn14
                          - wpick(e2_0, e2_1, p3) * rn24) * ip3;
            float e4_0 = q0 - f1_0 * rn14 - e2_0 * rn24 - e3_0 * rn34;
            float e4_1 = q1 - f1_1 * rn14 - e2_1 * rn24 - e3_1 * rn34;
            if (lane == p1)      e4_0 = rn14 - e2_0 * rn24 - e3_0 * rn34;
            if (lane + 32 == p1) e4_1 = rn14 - e2_1 * rn24 - e3_1 * rn34;
            if (lane == p2)      e4_0 = rn24 - e3_0 * rn34;
            if (lane + 32 == p2) e4_1 = rn24 - e3_1 * rn34;
            if (lane == p3)      e4_0 = rn34;
            if (lane + 32 == p3) e4_1 = rn34;
            int p4; float pv4;
            wargmax(e4_0, e4_1, u0, u1, lane, p4, pv4);
            if (p4 == lane) u0 = false;
            if (p4 == lane + 32) u1 = false;
            f4e[lane] = e4_0; f4e[lane + 32] = e4_1;

            if (lane == 0) {
                s_p[1] = p2; s_ip[1] = ip2; pivk[k + 1] = p2;
                s_p[2] = p3; s_ip[2] = ip3; pivk[k + 2] = p3;
                s_p[3] = p4; s_ip[3] = 1.0f / pv4; pivk[k + 3] = p4;
            }
        }
        __syncthreads();

        // Phase C: rank-4 update via fma.rn.f32x2 (negated multipliers)
        {
            int jj = tid & 127;
            int half = tid >> 7;
            int rb = half * 32;
            int p1 = s_p[0], p2 = s_p[1], p3 = s_p[2], p4 = s_p[3];
            float ip1 = s_ip[0], ip2 = s_ip[1], ip3 = s_ip[2], ip4 = s_ip[3];
            float* col = augT + jj * ILD;
            float rn1 = col[p1] * ip1;
            float rn2 = (col[p2] - f1[p2] * rn1) * ip2;
            float rn3 = (col[p3] - f1[p3] * rn1 - f2e[p3] * rn2) * ip3;
            float rn4 = (col[p4] - f1[p4] * rn1 - f2e[p4] * rn2 - f3e[p4] * rn3) * ip4;
            if (rn1 != 0.0f || rn2 != 0.0f || rn3 != 0.0f || rn4 != 0.0f) {
                u64t n1 = pk2(-rn1, -rn1), n2 = pk2(-rn2, -rn2);
                u64t n3 = pk2(-rn3, -rn3), n4 = pk2(-rn4, -rn4);
                #pragma unroll
                for (int i4 = rb; i4 < rb + 32; i4 += 4) {
                    ulonglong2 a1 = *(const ulonglong2*)&f1[i4];
                    ulonglong2 a2 = *(const ulonglong2*)&f2e[i4];
                    ulonglong2 a3 = *(const ulonglong2*)&f3e[i4];
                    ulonglong2 a4 = *(const ulonglong2*)&f4e[i4];
                    ulonglong2 v  = *(const ulonglong2*)&col[i4];
                    v.x = fma2(a1.x, n1, v.x);
                    v.x = fma2(a2.x, n2, v.x);
                    v.x = fma2(a3.x, n3, v.x);
                    v.x = fma2(a4.x, n4, v.x);
                    v.y = fma2(a1.y, n1, v.y);
                    v.y = fma2(a2.y, n2, v.y);
                    v.y = fma2(a3.y, n3, v.y);
                    v.y = fma2(a4.y, n4, v.y);
                    *(ulonglong2*)&col[i4] = v;
                }
                if ((p1 >> 5) == half)
                    col[p1] = rn1 - f2e[p1] * rn2 - f3e[p1] * rn3 - f4e[p1] * rn4;
                if ((p2 >> 5) == half)
                    col[p2] = rn2 - f3e[p2] * rn3 - f4e[p2] * rn4;
                if ((p3 >> 5) == half)
                    col[p3] = rn3 - f4e[p3] * rn4;
                if ((p4 >> 5) == half)
                    col[p4] = rn4;
            }
        }
        __syncthreads();
    }

    for (int idx = tid; idx < M_ * M_; idx += 256) {
        int kk = idx >> 6, c = idx & 63;
        float v = augT[(64 + c) * ILD + pivk[kk]];
        sS[kk * 65 + c] = v;
        __nv_bfloat16 h = __float2bfloat16(v);
        g_Whi[(size_t)b * 8192 + (size_t)(64 + kk) * 64 + c] = h;
        g_Wlo[(size_t)b * 8192 + (size_t)(64 + kk) * 64 + c] =
            __float2bfloat16(v - __bfloat162float(h));
    }
    __syncthreads();

    int tx = tid & 15, ty = tid >> 4;
    {
        float acc[4][4] = {};
        #pragma unroll 4
        for (int k = 0; k < M_; k++) {
            float xm[4], yn[4];
            #pragma unroll
            for (int i = 0; i < 4; i++) xm[i] = sS[(ty * 4 + i) * 65 + k];
            #pragma unroll
            for (int jj = 0; jj < 4; jj++) yn[jj] = sC[k * 64 + tx * 4 + jj];
            #pragma unroll
            for (int i = 0; i < 4; i++)
                #pragma unroll
                for (int jj = 0; jj < 4; jj++) acc[i][jj] += xm[i] * yn[jj];
        }
        #pragma unroll
        for (int i = 0; i < 4; i++)
            #pragma unroll
            for (int jj = 0; jj < 4; jj++)
                sT[(ty * 4 + i) * 65 + tx * 4 + jj] = acc[i][jj];
    }
    __syncthreads();
    {
        float acc[4][4] = {};
        #pragma unroll 4
        for (int k = 0; k < M_; k++) {
            float xm[4], yn[4];
            #pragma unroll
            for (int i = 0; i < 4; i++) xm[i] = sT[(ty * 4 + i) * 65 + k];
            #pragma unroll
            for (int jj = 0; jj < 4; jj++) yn[jj] = sS[k * 65 + tx * 4 + jj];
            #pragma unroll
            for (int i = 0; i < 4; i++)
                #pragma unroll
                for (int jj = 0; jj < 4; jj++) acc[i][jj] += xm[i] * yn[jj];
        }
        #pragma unroll
        for (int i = 0; i < 4; i++)
            #pragma unroll
            for (int jj = 0; jj < 4; jj++) {
                int r = ty * 4 + i, c = tx * 4 + jj;
                float v = acc[i][jj];
                __nv_bfloat16 h = __float2bfloat16(v);
                g_Whi[(size_t)b * 8192 + (size_t)r * 64 + c] = h;
                g_Wlo[(size_t)b * 8192 + (size_t)r * 64 + c] =
                    __float2bfloat16(v - __bfloat162float(h));
            }
    }
}

// ---------------- quadratic forms (R14 proven): mma.sync bf16 split, 16 warps ----------------
#define QNC 128
#define QOFF_WHI   0
#define QOFF_WLO   (QOFF_WHI + 128 * QLD * 2)
#define QOFF_BHI   (QOFF_WLO + 128 * QLD * 2)
#define QOFF_BLO   (QOFF_BHI + QNC * QLD * 2)
#define QOFF_SPART (QOFF_BLO + QNC * QLD * 2)
#define QSMEM_TOTAL (QOFF_SPART + 4 * QNC * 4)

__device__ __forceinline__ void mma16816(float d[4], const uint32_t a[4], const uint32_t b[2]) {
    asm volatile(
        "mma.sync.aligned.m16n8k16.row.col.f32.bf16.bf16.f32 "
        "{%0,%1,%2,%3}, {%4,%5,%6,%7}, {%8,%9}, {%0,%1,%2,%3};"
        : "+f"(d[0]), "+f"(d[1]), "+f"(d[2]), "+f"(d[3])
        : "r"(a[0]), "r"(a[1]), "r"(a[2]), "r"(a[3]), "r"(b[0]), "r"(b[1]));
}

__global__ void __launch_bounds__(512) k_quad_mma() {
    extern __shared__ char smem[];
    __nv_bfloat16* sWhi = (__nv_bfloat16*)(smem + QOFF_WHI);
    __nv_bfloat16* sWlo = (__nv_bfloat16*)(smem + QOFF_WLO);
    __nv_bfloat16* sBhi = (__nv_bfloat16*)(smem + QOFF_BHI);
    __nv_bfloat16* sBlo = (__nv_bfloat16*)(smem + QOFF_BLO);
    float* spart = (float*)(smem + QOFF_SPART);

    int tid = threadIdx.x;
    int wid = tid >> 5, lane = tid & 31;
    int wm = wid & 3;
    int wn = wid >> 2;
    int g0 = blockIdx.x * QNC;
    int b  = blockIdx.y;

    {
        const uint4* srcH = (const uint4*)(g_Whi + (size_t)b * 8192);
        const uint4* srcL = (const uint4*)(g_Wlo + (size_t)b * 8192);
        for (int i = tid; i < 1024; i += 512) {
            int r = i >> 3, c = i & 7;
            *(uint4*)&sWhi[r * QLD + c * 8] = srcH[i];
            *(uint4*)&sWlo[r * QLD + c * 8] = srcL[i];
        }
    }
    {
        const __nv_bfloat16* srcH = g_Bhi + (size_t)g0 * QLD;
        const __nv_bfloat16* srcL = g_Blo + (size_t)g0 * QLD;
        for (int i = tid; i < QNC * 8; i += 512) {
            int g = i >> 3, c = i & 7;
            *(uint4*)&sBhi[g * QLD + c * 8] = *(const uint4*)&srcH[(size_t)g * QLD + c * 8];
            *(uint4*)&sBlo[g * QLD + c * 8] = *(const uint4*)&srcL[(size_t)g * QLD + c * 8];
        }
    }
    __syncthreads();

    int lr = lane >> 2;
    int cq = (lane & 3) * 2;

    float d[2][4][4];
    #pragma unroll
    for (int f = 0; f < 2; f++)
        #pragma unroll
        for (int t = 0; t < 4; t++)
            #pragma unroll
            for (int q = 0; q < 4; q++) d[f][t][q] = 0.0f;

    #pragma unroll
    for (int sp = 0; sp < 3; sp++) {
        const __nv_bfloat16* Wsrc = (sp == 2) ? sWlo : sWhi;
        const __nv_bfloat16* Bsrc = (sp == 1) ? sBlo : sBhi;
        #pragma unroll
        for (int ks = 0; ks < 4; ks++) {
            int kb = ks * 16;
            uint32_t a[2][4];
            #pragma unroll
            for (int f = 0; f < 2; f++) {
                int r0 = wm * 32 + f * 16 + lr;
                a[f][0] = *(const uint32_t*)&Wsrc[r0 * QLD + kb + cq];
                a[f][1] = *(const uint32_t*)&Wsrc[(r0 + 8) * QLD + kb + cq];
                a[f][2] = *(const uint32_t*)&Wsrc[r0 * QLD + kb + cq + 8];
                a[f][3] = *(const uint32_t*)&Wsrc[(r0 + 8) * QLD + kb + cq + 8];
            }
            #pragma unroll
            for (int t = 0; t < 4; t++) {
                int gl = wn * 32 + t * 8 + lr;
                uint32_t bb[2];
                bb[0] = *(const uint32_t*)&Bsrc[gl * QLD + kb + cq];
                bb[1] = *(const uint32_t*)&Bsrc[gl * QLD + kb + cq + 8];
                mma16816(d[0][t], a[0], bb);
                mma16816(d[1][t], a[1], bb);
            }
        }
    }

    #pragma unroll
    for (int t = 0; t < 4; t++) {
        int gcol = wn * 32 + t * 8 + cq;
        float p0 = 0.0f, p1 = 0.0f;
        #pragma unroll
        for (int f = 0; f < 2; f++) {
            int m0 = (wm * 32 + f * 16 + lr) & 63;
            int m8 = m0 + 8;
            float a00 = __bfloat162float(sBhi[gcol * QLD + m0]) + __bfloat162float(sBlo[gcol * QLD + m0]);
            float a10 = __bfloat162float(sBhi[gcol * QLD + m8]) + __bfloat162float(sBlo[gcol * QLD + m8]);
            float a01 = __bfloat162float(sBhi[(gcol + 1) * QLD + m0]) + __bfloat162float(sBlo[(gcol + 1) * QLD + m0]);
            float a11 = __bfloat162float(sBhi[(gcol + 1) * QLD + m8]) + __bfloat162float(sBlo[(gcol + 1) * QLD + m8]);
            p0 += d[f][t][0] * a00 + d[f][t][2] * a10;
            p1 += d[f][t][1] * a01 + d[f][t][3] * a11;
        }
        #pragma unroll
        for (int o = 4; o < 32; o <<= 1) {
            p0 += __shfl_xor_sync(0xffffffffu, p0, o);
            p1 += __shfl_xor_sync(0xffffffffu, p1, o);
        }
        if (lane < 4) {
            spart[wm * QNC + gcol] = p0;
            spart[wm * QNC + gcol + 1] = p1;
        }
    }
    __syncthreads();
    if (tid < QNC) {
        int g = tid;
        float t1 = spart[g] + spart[QNC + g];
        float t2 = spart[2 * QNC + g] + spart[3 * QNC + g];
        g_T1[(size_t)b * G_ + g0 + g] = t1;
        g_T2[(size_t)b * G_ + g0 + g] = fabsf(t2);
    }
}

// ---------------- per-gridpoint MLP ----------------
__global__ void k_mlp(const float* __restrict__ W1, const float* __restrict__ B1,
                      const float* __restrict__ W2, const float* __restrict__ B2,
                      const float* __restrict__ W3, const float* __restrict__ B3,
                      int it, int last, float* __restrict__ out) {
    int g = blockIdx.x;
    int b = threadIdx.x;
    __shared__ float sW1[96], sB1[32], sW2[1024], sB2[32], sW3[32], sB3;
    size_t gidx = (size_t)it * G_ + g;
    const float* w1 = W1 + gidx * 96;
    const float* w2 = W2 + gidx * 1024;
    if (b < 96) sW1[b] = w1[b];
    if (b < 32) {
        sB1[b] = B1[gidx * 32 + b];
        sB2[b] = B2[gidx * 32 + b];
        sW3[b] = W3[gidx * 32 + b];
    }
    if (b == 0) sB3 = B3[gidx];
    for (int i = b; i < 1024; i += 128) sW2[i] = w2[i];
    __syncthreads();

    float x0 = g_T1[(size_t)b * G_ + g];
    float x1 = g_T2[(size_t)b * G_ + g];
    float x2 = g_g[(size_t)b * G_ + g];

    float h[HID_];
    #pragma unroll
    for (int j = 0; j < HID_; j++) {
        float v = x0 * sW1[j] + x1 * sW1[32 + j] + x2 * sW1[64 + j] + sB1[j];
        h[j] = fmaxf(v, 0.0f);
    }
    float h2[HID_];
    #pragma unroll
    for (int j = 0; j < HID_; j++) h2[j] = sB2[j];
    #pragma unroll
    for (int j = 0; j < HID_; j++) {
        float hv = h[j];
        #pragma unroll
        for (int k = 0; k < HID_; k++) h2[k] += hv * sW2[j * 32 + k];
    }
    float o = sB3;
    #pragma unroll
    for (int k = 0; k < HID_; k++) o += fmaxf(h2[k], 0.0f) * sW3[k];

    if (last) out[(size_t)b * G_ + g] = o;
    else      g_g[(size_t)b * G_ + g] = o;
}

// ---------------- launch ----------------
extern "C" void kernel_launch(void* const* d_in, const int* in_sizes, int n_in,
                              void* d_out, int out_size) {
    const float* data = (const float*)d_in[0];
    const float* A    = (const float*)d_in[1];
    const float* W1   = (const float*)d_in[2];
    const float* b1   = (const float*)d_in[3];
    const float* W2   = (const float*)d_in[4];
    const float* b2   = (const float*)d_in[5];
    const float* W3   = (const float*)d_in[6];
    const float* b3   = (const float*)d_in[7];
    float* out = (float*)d_out;

    static int smem_set = 0;
    if (!smem_set) {
        cudaFuncSetAttribute(k_quad_mma, cudaFuncAttributeMaxDynamicSharedMemorySize, QSMEM_TOTAL);
        cudaFuncSetAttribute(k_inv_mm, cudaFuncAttributeMaxDynamicSharedMemorySize, IMSMEM);
        smem_set = 1;
    }

    k_presplitA<<<G_ / 32, 256>>>(A);
    k_datacov<<<B_, 256>>>(data);
    for (int it = 0; it < 3; it++) {
        k_cov<<<dim3(B_, KSPLIT), 256>>>(A);
        k_inv_mm<<<B_, 256, IMSMEM>>>();
        k_quad_mma<<<dim3(G_ / QNC, B_), 512, QSMEM_TOTAL>>>();
        k_mlp<<<G_, 128>>>(W1, b1, W2, b2, W3, b3, it, it == 2 ? 1 : 0, out);
    }
}